// round 4
// baseline (speedup 1.0000x reference)
#include <cuda_runtime.h>
#include <cstdint>

// Problem constants (match reference)
#define B_DIM 16
#define N_DIM 2048
#define S_DIM 4096
#define D_DIM 128
#define NNZ_DIM 1048576

// ---------------------------------------------------------------------------
// Zero-fill the output: B*N*D = 4,194,304 floats = 1,048,576 float4s.
// ---------------------------------------------------------------------------
__global__ void zero_out_kernel(float4* __restrict__ out, int n4) {
    int i = blockIdx.x * blockDim.x + threadIdx.x;
    if (i < n4) out[i] = make_float4(0.f, 0.f, 0.f, 0.f);
}

// ---------------------------------------------------------------------------
// One warp per NNZ entry. Each lane handles 4 floats of the D=128 row:
//   - coalesced float4 gather from emb_table (L2-resident, 25.7 MB)
//   - scale by mask_values[e]
//   - red.global.add.v4.f32 into the destination row (L2-resident, 16 MB)
// Index loads are warp-uniform (broadcast).
// ---------------------------------------------------------------------------
__global__ void __launch_bounds__(256)
scatter_pool_kernel(const int*   __restrict__ subnode_ids,   // [B*S]
                    const int*   __restrict__ mask_batch,    // [NNZ]
                    const int*   __restrict__ mask_node,     // [NNZ]
                    const int*   __restrict__ mask_subnode,  // [NNZ]
                    const float* __restrict__ mask_values,   // [NNZ]
                    const float* __restrict__ emb,           // [VOCAB*D]
                    float*       __restrict__ out)           // [B*N*D]
{
    const int warp_id = (blockIdx.x * blockDim.x + threadIdx.x) >> 5;
    const int lane    = threadIdx.x & 31;
    if (warp_id >= NNZ_DIM) return;

    const int   b  = __ldg(mask_batch   + warp_id);
    const int   nd = __ldg(mask_node    + warp_id);
    const int   s  = __ldg(mask_subnode + warp_id);
    const float v  = __ldg(mask_values  + warp_id);
    const int   tok = __ldg(subnode_ids + b * S_DIM + s);

    const float4* src = reinterpret_cast<const float4*>(
                            emb + (size_t)tok * D_DIM) + lane;
    float4 e = __ldg(src);

    float4* dst = reinterpret_cast<float4*>(
                      out + ((size_t)b * N_DIM + nd) * D_DIM) + lane;

    asm volatile("red.global.add.v4.f32 [%0], {%1, %2, %3, %4};"
                 :: "l"(dst), "f"(e.x * v), "f"(e.y * v),
                    "f"(e.z * v), "f"(e.w * v)
                 : "memory");
}

// ---------------------------------------------------------------------------
// Harness entry. Inputs (metadata order):
//   0: subnode_ids  int32  [B,S]
//   1: mask_batch   int32  [NNZ]
//   2: mask_node    int32  [NNZ]
//   3: mask_subnode int32  [NNZ]
//   4: mask_values  fp32   [NNZ]
//   5: emb_table    fp32   [VOCAB,D]
// out: fp32 [B,N,D]
// ---------------------------------------------------------------------------
extern "C" void kernel_launch(void* const* d_in, const int* in_sizes, int n_in,
                              void* d_out, int out_size) {
    const int*   subnode_ids  = (const int*)  d_in[0];
    const int*   mask_batch   = (const int*)  d_in[1];
    const int*   mask_node    = (const int*)  d_in[2];
    const int*   mask_subnode = (const int*)  d_in[3];
    const float* mask_values  = (const float*)d_in[4];
    const float* emb_table    = (const float*)d_in[5];
    float*       out          = (float*)      d_out;

    // 1) zero the (poisoned) output
    const int n4 = out_size / 4;  // float4 count
    zero_out_kernel<<<(n4 + 255) / 256, 256>>>((float4*)out, n4);

    // 2) fused gather+scale+scatter-add: one warp per entry
    //    NNZ warps = NNZ*32 threads; 256 thr/block -> 8 entries/block
    const int blocks = (NNZ_DIM * 32) / 256;  // 131072, exact
    scatter_pool_kernel<<<blocks, 256>>>(subnode_ids, mask_batch, mask_node,
                                         mask_subnode, mask_values,
                                         emb_table, out);
}